// round 1
// baseline (speedup 1.0000x reference)
#include <cuda_runtime.h>
#include <cstddef>

#define D_MODEL 1024
#define NUM_HEADS 16
#define HEAD_DIM 64
#define S_LEN 2048
#define BATCH 2
#define M_ROWS (BATCH * S_LEN)      // 4096

// Scratch (static device globals — no allocation at runtime)
__device__ float g_Q[BATCH * NUM_HEADS * S_LEN * HEAD_DIM];
__device__ float g_K[BATCH * NUM_HEADS * S_LEN * HEAD_DIM];
__device__ float g_V[BATCH * NUM_HEADS * S_LEN * HEAD_DIM];
__device__ float g_AO[M_ROWS * D_MODEL];

// ---------------------------------------------------------------------------
// SGEMM 128x128x8, C[m,n] = sum_k A[m,k]*W[n,k] (+bias). A:[M,K], W:[N,K].
// QKV variant scatters into g_Q/g_K/g_V with per-head layout [B,H,S,hd].
// ---------------------------------------------------------------------------
__global__ __launch_bounds__(256) void sgemm_qkv(
    const float* __restrict__ A, const float* __restrict__ W,
    const float* __restrict__ bias, int M, int N, int K)
{
    __shared__ float As[8][128];
    __shared__ float Bs[8][128];
    const int t  = threadIdx.x;
    const int tx = t & 15, ty = t >> 4;
    const int m0 = blockIdx.y * 128, n0 = blockIdx.x * 128;
    const int lrow = t >> 1;
    const int lk   = (t & 1) * 4;
    const float* Ag = A + (size_t)(m0 + lrow) * K + lk;
    const float* Wg = W + (size_t)(n0 + lrow) * K + lk;

    float acc[8][8];
#pragma unroll
    for (int i = 0; i < 8; i++)
#pragma unroll
        for (int j = 0; j < 8; j++) acc[i][j] = 0.f;

    for (int kt = 0; kt < K; kt += 8) {
        float4 av = *(const float4*)(Ag + kt);
        float4 wv = *(const float4*)(Wg + kt);
        __syncthreads();
        As[lk + 0][lrow] = av.x; As[lk + 1][lrow] = av.y;
        As[lk + 2][lrow] = av.z; As[lk + 3][lrow] = av.w;
        Bs[lk + 0][lrow] = wv.x; Bs[lk + 1][lrow] = wv.y;
        Bs[lk + 2][lrow] = wv.z; Bs[lk + 3][lrow] = wv.w;
        __syncthreads();
#pragma unroll
        for (int k = 0; k < 8; k++) {
            float4 a0 = *(const float4*)&As[k][ty * 8];
            float4 a1 = *(const float4*)&As[k][ty * 8 + 4];
            float4 b0 = *(const float4*)&Bs[k][tx * 8];
            float4 b1 = *(const float4*)&Bs[k][tx * 8 + 4];
            float a[8] = {a0.x, a0.y, a0.z, a0.w, a1.x, a1.y, a1.z, a1.w};
            float b[8] = {b0.x, b0.y, b0.z, b0.w, b1.x, b1.y, b1.z, b1.w};
#pragma unroll
            for (int i = 0; i < 8; i++)
#pragma unroll
                for (int j = 0; j < 8; j++) acc[i][j] += a[i] * b[j];
        }
    }

    // Epilogue: add bias, scatter to Q/K/V [B,H,S,hd]
#pragma unroll
    for (int i = 0; i < 8; i++) {
        int m  = m0 + ty * 8 + i;
        int bb = m >> 11;          // /2048
        int s  = m & 2047;
#pragma unroll
        for (int j = 0; j < 8; j++) {
            int n = n0 + tx * 8 + j;
            float v = acc[i][j] + bias[n];
            int h = n / 192;
            int r = n - h * 192;
            size_t off = (((size_t)bb * NUM_HEADS + h) * S_LEN + s) * HEAD_DIM;
            if (r < 64)       g_Q[off + r]       = v;
            else if (r < 128) g_K[off + r - 64]  = v;
            else              g_V[off + r - 128] = v;
        }
    }
}

__global__ __launch_bounds__(256) void sgemm_out(
    const float* __restrict__ A, const float* __restrict__ W,
    const float* __restrict__ bias, float* __restrict__ C, int M, int N, int K)
{
    __shared__ float As[8][128];
    __shared__ float Bs[8][128];
    const int t  = threadIdx.x;
    const int tx = t & 15, ty = t >> 4;
    const int m0 = blockIdx.y * 128, n0 = blockIdx.x * 128;
    const int lrow = t >> 1;
    const int lk   = (t & 1) * 4;
    const float* Ag = A + (size_t)(m0 + lrow) * K + lk;
    const float* Wg = W + (size_t)(n0 + lrow) * K + lk;

    float acc[8][8];
#pragma unroll
    for (int i = 0; i < 8; i++)
#pragma unroll
        for (int j = 0; j < 8; j++) acc[i][j] = 0.f;

    for (int kt = 0; kt < K; kt += 8) {
        float4 av = *(const float4*)(Ag + kt);
        float4 wv = *(const float4*)(Wg + kt);
        __syncthreads();
        As[lk + 0][lrow] = av.x; As[lk + 1][lrow] = av.y;
        As[lk + 2][lrow] = av.z; As[lk + 3][lrow] = av.w;
        Bs[lk + 0][lrow] = wv.x; Bs[lk + 1][lrow] = wv.y;
        Bs[lk + 2][lrow] = wv.z; Bs[lk + 3][lrow] = wv.w;
        __syncthreads();
#pragma unroll
        for (int k = 0; k < 8; k++) {
            float4 a0 = *(const float4*)&As[k][ty * 8];
            float4 a1 = *(const float4*)&As[k][ty * 8 + 4];
            float4 b0 = *(const float4*)&Bs[k][tx * 8];
            float4 b1 = *(const float4*)&Bs[k][tx * 8 + 4];
            float a[8] = {a0.x, a0.y, a0.z, a0.w, a1.x, a1.y, a1.z, a1.w};
            float b[8] = {b0.x, b0.y, b0.z, b0.w, b1.x, b1.y, b1.z, b1.w};
#pragma unroll
            for (int i = 0; i < 8; i++)
#pragma unroll
                for (int j = 0; j < 8; j++) acc[i][j] += a[i] * b[j];
        }
    }

#pragma unroll
    for (int i = 0; i < 8; i++) {
        int m = m0 + ty * 8 + i;
        float* crow = C + (size_t)m * N + n0 + tx * 8;
        float4 v0, v1;
        v0.x = acc[i][0] + bias[n0 + tx * 8 + 0];
        v0.y = acc[i][1] + bias[n0 + tx * 8 + 1];
        v0.z = acc[i][2] + bias[n0 + tx * 8 + 2];
        v0.w = acc[i][3] + bias[n0 + tx * 8 + 3];
        v1.x = acc[i][4] + bias[n0 + tx * 8 + 4];
        v1.y = acc[i][5] + bias[n0 + tx * 8 + 5];
        v1.z = acc[i][6] + bias[n0 + tx * 8 + 6];
        v1.w = acc[i][7] + bias[n0 + tx * 8 + 7];
        *(float4*)(crow)     = v0;
        *(float4*)(crow + 4) = v1;
    }
}

// ---------------------------------------------------------------------------
// Fused flash attention, fp32. Per block: (b, h, 64 query rows).
// Online softmax; K/V tiles of 64 rows; microtiles 4x4 per thread.
// Scores: rows r_i = ty+16i, cols c_j = tx+16j (bank-friendly interleave).
// Output: rows r_i = ty+16i, cols d_j = tx*4+j.
// ---------------------------------------------------------------------------
#define PADQ 68
#define FLASH_SMEM (4 * 64 * PADQ * 4)

__global__ __launch_bounds__(256, 2) void flash_kernel(float* __restrict__ O)
{
    extern __shared__ float sm[];
    float* Qs = sm;                 // [64][PADQ]
    float* Ks = Qs + 64 * PADQ;     // [64][PADQ]
    float* Vs = Ks + 64 * PADQ;     // [64][PADQ]
    float* Ps = Vs + 64 * PADQ;     // [64][PADQ]

    const int t  = threadIdx.x;
    const int tx = t & 15, ty = t >> 4;
    const int b  = blockIdx.z, h = blockIdx.y;
    const int q0 = blockIdx.x * 64;
    const float scale = 0.125f;     // 1/sqrt(64)

    const size_t base = ((size_t)(b * NUM_HEADS + h)) * S_LEN * HEAD_DIM;
    const float* Qg = g_Q + base + (size_t)q0 * HEAD_DIM;

    // Load Q tile (64x64) into shared, natural layout
#pragma unroll
    for (int i = 0; i < 4; i++) {
        int idx4 = t + 256 * i;
        int row  = idx4 >> 4;
        int dq   = (idx4 & 15) * 4;
        *(float4*)(Qs + row * PADQ + dq) = *(const float4*)(Qg + row * HEAD_DIM + dq);
    }

    float m_i[4], l_i[4], o[4][4];
#pragma unroll
    for (int i = 0; i < 4; i++) {
        m_i[i] = -1e30f; l_i[i] = 0.f;
#pragma unroll
        for (int j = 0; j < 4; j++) o[i][j] = 0.f;
    }

    for (int kt = 0; kt < S_LEN; kt += 64) {
        __syncthreads();
        const float* Kg = g_K + base + (size_t)kt * HEAD_DIM;
        const float* Vg = g_V + base + (size_t)kt * HEAD_DIM;
#pragma unroll
        for (int i = 0; i < 4; i++) {
            int idx4 = t + 256 * i;
            int row  = idx4 >> 4;
            int dq   = (idx4 & 15) * 4;
            *(float4*)(Ks + row * PADQ + dq) = *(const float4*)(Kg + row * HEAD_DIM + dq);
            *(float4*)(Vs + row * PADQ + dq) = *(const float4*)(Vg + row * HEAD_DIM + dq);
        }
        __syncthreads();

        // Scores: s[i][j] = Q[r_i] . K[c_j]
        float s[4][4];
#pragma unroll
        for (int i = 0; i < 4; i++)
#pragma unroll
            for (int j = 0; j < 4; j++) s[i][j] = 0.f;

#pragma unroll 4
        for (int d = 0; d < 64; d += 4) {
            float4 a[4], bb[4];
#pragma unroll
            for (int i = 0; i < 4; i++) a[i]  = *(const float4*)(Qs + (ty + 16 * i) * PADQ + d);
#pragma unroll
            for (int j = 0; j < 4; j++) bb[j] = *(const float4*)(Ks + (tx + 16 * j) * PADQ + d);
#pragma unroll
            for (int i = 0; i < 4; i++)
#pragma unroll
                for (int j = 0; j < 4; j++) {
                    s[i][j] += a[i].x * bb[j].x;
                    s[i][j] += a[i].y * bb[j].y;
                    s[i][j] += a[i].z * bb[j].z;
                    s[i][j] += a[i].w * bb[j].w;
                }
        }

        // Online softmax per row r_i (16-lane reduce across tx)
#pragma unroll
        for (int i = 0; i < 4; i++) {
#pragma unroll
            for (int j = 0; j < 4; j++) s[i][j] *= scale;
            float mx = fmaxf(fmaxf(s[i][0], s[i][1]), fmaxf(s[i][2], s[i][3]));
#pragma unroll
            for (int off = 8; off >= 1; off >>= 1)
                mx = fmaxf(mx, __shfl_xor_sync(0xffffffffu, mx, off));
            float m_new = fmaxf(m_i[i], mx);
            float corr  = __expf(m_i[i] - m_new);
            float rs = 0.f;
#pragma unroll
            for (int j = 0; j < 4; j++) {
                s[i][j] = __expf(s[i][j] - m_new);
                rs += s[i][j];
            }
#pragma unroll
            for (int off = 8; off >= 1; off >>= 1)
                rs += __shfl_xor_sync(0xffffffffu, rs, off);
            l_i[i] = l_i[i] * corr + rs;
            m_i[i] = m_new;
#pragma unroll
            for (int j = 0; j < 4; j++) o[i][j] *= corr;
            // store probabilities to shared for PV GEMM
#pragma unroll
            for (int j = 0; j < 4; j++)
                Ps[(ty + 16 * i) * PADQ + tx + 16 * j] = s[i][j];
        }
        __syncthreads();

        // O += P @ V : o[i][j] += sum_k P[r_i][k] * V[k][tx*4+j]
#pragma unroll 4
        for (int k = 0; k < 64; k += 4) {
            float4 a[4];
#pragma unroll
            for (int i = 0; i < 4; i++) a[i] = *(const float4*)(Ps + (ty + 16 * i) * PADQ + k);
#pragma unroll
            for (int u = 0; u < 4; u++) {
                float4 bv = *(const float4*)(Vs + (k + u) * PADQ + tx * 4);
#pragma unroll
                for (int i = 0; i < 4; i++) {
                    float av = ((const float*)&a[i])[u];
                    o[i][0] += av * bv.x;
                    o[i][1] += av * bv.y;
                    o[i][2] += av * bv.z;
                    o[i][3] += av * bv.w;
                }
            }
        }
    }

    // Epilogue: normalize and write to [B,S,D] interleaved layout
#pragma unroll
    for (int i = 0; i < 4; i++) {
        float inv = 1.f / l_i[i];
        int r = ty + 16 * i;
        float4 v;
        v.x = o[i][0] * inv; v.y = o[i][1] * inv;
        v.z = o[i][2] * inv; v.w = o[i][3] * inv;
        *(float4*)(O + ((size_t)(b * S_LEN + q0 + r)) * D_MODEL + h * HEAD_DIM + tx * 4) = v;
    }
}

// ---------------------------------------------------------------------------
extern "C" void kernel_launch(void* const* d_in, const int* in_sizes, int n_in,
                              void* d_out, int out_size)
{
    const float* X    = (const float*)d_in[0];
    const float* Wqkv = (const float*)d_in[1];
    const float* bqkv = (const float*)d_in[2];
    const float* Wo   = (const float*)d_in[3];
    const float* bo   = (const float*)d_in[4];
    float* out = (float*)d_out;

    cudaFuncSetAttribute((const void*)flash_kernel,
                         cudaFuncAttributeMaxDynamicSharedMemorySize, FLASH_SMEM);

    // 1) QKV projection + scatter: [4096,1024] @ [3072,1024]^T
    sgemm_qkv<<<dim3(3 * D_MODEL / 128, M_ROWS / 128), 256>>>(
        X, Wqkv, bqkv, M_ROWS, 3 * D_MODEL, D_MODEL);

    // 2) Fused flash attention -> g_AO [B,S,D]
    float* aoPtr = nullptr;
    cudaGetSymbolAddress((void**)&aoPtr, g_AO);
    flash_kernel<<<dim3(S_LEN / 64, NUM_HEADS, BATCH), 256, FLASH_SMEM>>>(aoPtr);

    // 3) Output projection: [4096,1024] @ [1024,1024]^T -> d_out
    sgemm_out<<<dim3(D_MODEL / 128, M_ROWS / 128), 256>>>(
        aoPtr, Wo, bo, out, M_ROWS, D_MODEL, D_MODEL);
}

// round 3
// speedup vs baseline: 2.5355x; 2.5355x over previous
#include <cuda_runtime.h>
#include <cuda_bf16.h>
#include <cstdint>
#include <cstddef>

#define D_MODEL 1024
#define NUM_HEADS 16
#define HEAD_DIM 64
#define S_LEN 2048
#define BATCH 2
#define M_ROWS (BATCH * S_LEN)      // 4096

// ---------------------------------------------------------------------------
// Scratch (static device globals)
// ---------------------------------------------------------------------------
__device__ __nv_bfloat16 g_Qhi[BATCH * NUM_HEADS * S_LEN * HEAD_DIM];
__device__ __nv_bfloat16 g_Qlo[BATCH * NUM_HEADS * S_LEN * HEAD_DIM];
__device__ __nv_bfloat16 g_Khi[BATCH * NUM_HEADS * S_LEN * HEAD_DIM];
__device__ __nv_bfloat16 g_Klo[BATCH * NUM_HEADS * S_LEN * HEAD_DIM];
__device__ __nv_bfloat16 g_Vhi[BATCH * NUM_HEADS * S_LEN * HEAD_DIM];
__device__ __nv_bfloat16 g_Vlo[BATCH * NUM_HEADS * S_LEN * HEAD_DIM];
__device__ __nv_bfloat16 g_Xhi[M_ROWS * D_MODEL];
__device__ __nv_bfloat16 g_Xlo[M_ROWS * D_MODEL];
__device__ __nv_bfloat16 g_Wqkvhi[3 * D_MODEL * D_MODEL];
__device__ __nv_bfloat16 g_Wqkvlo[3 * D_MODEL * D_MODEL];
__device__ __nv_bfloat16 g_Wohi[D_MODEL * D_MODEL];
__device__ __nv_bfloat16 g_Wolo[D_MODEL * D_MODEL];
__device__ __nv_bfloat16 g_AOhi[M_ROWS * D_MODEL];
__device__ __nv_bfloat16 g_AOlo[M_ROWS * D_MODEL];

// ---------------------------------------------------------------------------
// Helpers
// ---------------------------------------------------------------------------
__device__ __forceinline__ uint32_t s2u(const void* p) {
    uint32_t a;
    asm("{ .reg .u64 t; cvta.to.shared.u64 t, %1; cvt.u32.u64 %0, t; }"
        : "=r"(a) : "l"(p));
    return a;
}
__device__ __forceinline__ void cpa16(uint32_t dst, const void* src) {
    asm volatile("cp.async.cg.shared.global [%0], [%1], 16;\n"
                 :: "r"(dst), "l"(src));
}
__device__ __forceinline__ void cpa_commit() {
    asm volatile("cp.async.commit_group;\n" ::: "memory");
}
template <int N>
__device__ __forceinline__ void cpa_wait() {
    asm volatile("cp.async.wait_group %0;\n" :: "n"(N) : "memory");
}
__device__ __forceinline__ void ldsm4(uint32_t* r, uint32_t a) {
    asm volatile("ldmatrix.sync.aligned.m8n8.x4.shared.b16 {%0,%1,%2,%3}, [%4];"
                 : "=r"(r[0]), "=r"(r[1]), "=r"(r[2]), "=r"(r[3]) : "r"(a));
}
__device__ __forceinline__ void ldsm4t(uint32_t* r, uint32_t a) {
    asm volatile("ldmatrix.sync.aligned.m8n8.x4.trans.shared.b16 {%0,%1,%2,%3}, [%4];"
                 : "=r"(r[0]), "=r"(r[1]), "=r"(r[2]), "=r"(r[3]) : "r"(a));
}
__device__ __forceinline__ void mma16816(float* c, const uint32_t* a, const uint32_t* b) {
    asm volatile(
        "mma.sync.aligned.m16n8k16.row.col.f32.bf16.bf16.f32 "
        "{%0,%1,%2,%3}, {%4,%5,%6,%7}, {%8,%9}, {%0,%1,%2,%3};"
        : "+f"(c[0]), "+f"(c[1]), "+f"(c[2]), "+f"(c[3])
        : "r"(a[0]), "r"(a[1]), "r"(a[2]), "r"(a[3]), "r"(b[0]), "r"(b[1]));
}

// fast e^x via FFMA pipe (x <= ~0); accurate to ~2e-7 rel
__device__ __forceinline__ float fexp(float x) {
    x = fmaxf(x, -80.0f);
    float y = x * 1.4426950408889634f;
    float r = __fadd_rn(y, 12582912.0f);
    int   n = __float_as_int(r) - 0x4B400000;
    float f = y - __fsub_rn(r, 12582912.0f);
    float p = 1.5403e-4f;
    p = fmaf(p, f, 1.3333558e-3f);
    p = fmaf(p, f, 9.6181291e-3f);
    p = fmaf(p, f, 5.5504109e-2f);
    p = fmaf(p, f, 2.4022651e-1f);
    p = fmaf(p, f, 6.9314718e-1f);
    p = fmaf(p, f, 1.0f);
    return __int_as_float(__float_as_int(p) + (n << 23));
}

__device__ __forceinline__ void split_store(float v0, float v1,
                                            __nv_bfloat16* hi, __nv_bfloat16* lo,
                                            size_t off) {
    __nv_bfloat16 h0 = __float2bfloat16(v0), h1 = __float2bfloat16(v1);
    __nv_bfloat162 H; H.x = h0; H.y = h1;
    *reinterpret_cast<__nv_bfloat162*>(hi + off) = H;
    __nv_bfloat162 L;
    L.x = __float2bfloat16(v0 - __bfloat162float(h0));
    L.y = __float2bfloat16(v1 - __bfloat162float(h1));
    *reinterpret_cast<__nv_bfloat162*>(lo + off) = L;
}

// swizzles: rows of 64B (4 x 16B chunks) / 128B (8 x 16B chunks)
#define SWA(row, ch) ((row) * 64 + ((((ch) ^ (((row) >> 1) & 3))) << 4))
#define SWF(row, ch) ((row) * 128 + ((((ch) ^ ((row) & 7))) << 4))

// ---------------------------------------------------------------------------
// Split fp32 -> bf16 hi + lo
// ---------------------------------------------------------------------------
__global__ __launch_bounds__(256) void split_kernel(
    const float* __restrict__ in, __nv_bfloat16* __restrict__ hi,
    __nv_bfloat16* __restrict__ lo, int n4)
{
    int i = blockIdx.x * blockDim.x + threadIdx.x;
    if (i >= n4) return;
    float4 v = ((const float4*)in)[i];
    split_store(v.x, v.y, hi, lo, (size_t)i * 4);
    split_store(v.z, v.w, hi, lo, (size_t)i * 4 + 2);
}

// ---------------------------------------------------------------------------
// mma.sync split-bf16 GEMM: C[4096, N] = A @ W^T + bias. 128x128 block,
// BK=32, 4-stage cp.async. K' = 3*1024 (Ahi*Whi, Ahi*Wlo, Alo*Whi).
// mode 0: scatter into Q/K/V hi/lo (Q pre-scaled 0.125); mode 1: fp32 out.
// ---------------------------------------------------------------------------
#define G_STAGE 16384
#define GEMM_SMEM (4 * G_STAGE)

__device__ __forceinline__ void g_load_stage(
    int c, int s, uint32_t smb, int t, int m0, int n0,
    const __nv_bfloat16* Ahi, const __nv_bfloat16* Alo,
    const __nv_bfloat16* Bhi, const __nv_bfloat16* Blo)
{
    int ph = c >> 5;
    int kc = (c & 31) * 32;
    const __nv_bfloat16* Ag = (ph == 2) ? Alo : Ahi;
    const __nv_bfloat16* Bg = (ph == 1) ? Blo : Bhi;
    uint32_t sa = smb + s * G_STAGE;
    uint32_t sb = sa + 8192;
#pragma unroll
    for (int i = 0; i < 2; i++) {
        int idx = t + 256 * i;
        int row = idx >> 2, cc = idx & 3;
        cpa16(sa + SWA(row, cc), Ag + (size_t)(m0 + row) * D_MODEL + kc + cc * 8);
    }
#pragma unroll
    for (int i = 0; i < 2; i++) {
        int idx = t + 256 * i;
        int row = idx >> 2, cc = idx & 3;
        cpa16(sb + SWA(row, cc), Bg + (size_t)(n0 + row) * D_MODEL + kc + cc * 8);
    }
    cpa_commit();
}

__global__ __launch_bounds__(256) void gemm_mma(
    const __nv_bfloat16* __restrict__ Ahi, const __nv_bfloat16* __restrict__ Alo,
    const __nv_bfloat16* __restrict__ Bhi, const __nv_bfloat16* __restrict__ Blo,
    const float* __restrict__ bias, float* __restrict__ Cout, int mode)
{
    extern __shared__ char sm[];
    uint32_t smb = s2u(sm);
    const int t = threadIdx.x, wid = t >> 5, lane = t & 31;
    const int g = lane >> 2, tg = lane & 3;
    const int warp_m = wid & 1, warp_n = wid >> 1;
    const int m0 = blockIdx.y * 128, n0 = blockIdx.x * 128;

    float acc[4][4][4];
#pragma unroll
    for (int a = 0; a < 4; a++)
#pragma unroll
        for (int b = 0; b < 4; b++)
#pragma unroll
            for (int k = 0; k < 4; k++) acc[a][b][k] = 0.f;

    g_load_stage(0, 0, smb, t, m0, n0, Ahi, Alo, Bhi, Blo);
    g_load_stage(1, 1, smb, t, m0, n0, Ahi, Alo, Bhi, Blo);
    g_load_stage(2, 2, smb, t, m0, n0, Ahi, Alo, Bhi, Blo);

    for (int c = 0; c < 96; c++) {
        if (c < 94) cpa_wait<2>();
        else if (c == 94) cpa_wait<1>();
        else cpa_wait<0>();
        __syncthreads();
        if (c + 3 < 96)
            g_load_stage(c + 3, (c + 3) & 3, smb, t, m0, n0, Ahi, Alo, Bhi, Blo);

        uint32_t sa = smb + (c & 3) * G_STAGE;
        uint32_t sb = sa + 8192;
#pragma unroll
        for (int ks = 0; ks < 2; ks++) {
            int cc = ks * 2;
            uint32_t af[4][4];
#pragma unroll
            for (int mt = 0; mt < 4; mt++) {
                int row = warp_m * 64 + mt * 16 + (lane & 15);
                int ch = cc + (lane >> 4);
                ldsm4(af[mt], sa + SWA(row, ch));
            }
            uint32_t bf[4][2];
#pragma unroll
            for (int bt = 0; bt < 2; bt++) {
                int row = warp_n * 32 + bt * 16 + ((lane >> 4) << 3) + (lane & 7);
                int ch = cc + ((lane >> 3) & 1);
                uint32_t r4[4];
                ldsm4(r4, sb + SWA(row, ch));
                bf[2 * bt][0] = r4[0]; bf[2 * bt][1] = r4[1];
                bf[2 * bt + 1][0] = r4[2]; bf[2 * bt + 1][1] = r4[3];
            }
#pragma unroll
            for (int mt = 0; mt < 4; mt++)
#pragma unroll
                for (int nt = 0; nt < 4; nt++)
                    mma16816(acc[mt][nt], af[mt], bf[nt]);
        }
    }

    // Epilogue
#pragma unroll
    for (int mt = 0; mt < 4; mt++) {
#pragma unroll
        for (int nt = 0; nt < 4; nt++) {
            int n = n0 + warp_n * 32 + nt * 8 + tg * 2;
            float b0 = bias[n], b1 = bias[n + 1];
            int mrow = m0 + warp_m * 64 + mt * 16 + g;
            if (mode == 1) {
#pragma unroll
                for (int hh = 0; hh < 2; hh++) {
                    int m = mrow + hh * 8;
                    float2 v;
                    v.x = acc[mt][nt][hh * 2] + b0;
                    v.y = acc[mt][nt][hh * 2 + 1] + b1;
                    *(float2*)(Cout + (size_t)m * D_MODEL + n) = v;
                }
            } else {
                int h = n / 192;
                int r = n - h * 192;
                __nv_bfloat16 *dhi, *dlo; int d; float sc = 1.f;
                if (r < 64)       { dhi = g_Qhi; dlo = g_Qlo; d = r; sc = 0.125f; }
                else if (r < 128) { dhi = g_Khi; dlo = g_Klo; d = r - 64; }
                else              { dhi = g_Vhi; dlo = g_Vlo; d = r - 128; }
#pragma unroll
                for (int hh = 0; hh < 2; hh++) {
                    int m = mrow + hh * 8;
                    int bb = m >> 11, s = m & 2047;
                    size_t off = (((size_t)(bb * NUM_HEADS + h)) * S_LEN + s) * HEAD_DIM + d;
                    float v0 = (acc[mt][nt][hh * 2] + b0) * sc;
                    float v1 = (acc[mt][nt][hh * 2 + 1] + b1) * sc;
                    split_store(v0, v1, dhi, dlo, off);
                }
            }
        }
    }
}

// ---------------------------------------------------------------------------
// Flash attention with mma.sync bf16 + split correction, poly-exp softmax.
// Block: (b, h, 64 q rows), 256 threads = 8 warps (4 m-tiles x 2 n-halves).
// ---------------------------------------------------------------------------
#define FQHI 0
#define FQLO 8192
#define FKV  16384           // stage: KHI, +8192 KLO, +16384 VHI, +24576 VLO
#define FKV_STAGE 32768
#define FPHI 81920
#define FPLO 90112
#define FREDM 98304
#define FREDS 98816
#define FLASH_SMEM 99328

__device__ __forceinline__ void f_load_kv(int it, int s, uint32_t smb, int t,
                                          size_t hb)
{
    size_t base = hb + (size_t)it * 64 * HEAD_DIM;
    uint32_t sb = smb + FKV + s * FKV_STAGE;
    const __nv_bfloat16* srcs[4] = {g_Khi, g_Klo, g_Vhi, g_Vlo};
#pragma unroll
    for (int a = 0; a < 4; a++) {
#pragma unroll
        for (int i = 0; i < 2; i++) {
            int idx = t + 256 * i;
            int row = idx >> 3, cc = idx & 7;
            cpa16(sb + a * 8192 + SWF(row, cc), srcs[a] + base + row * HEAD_DIM + cc * 8);
        }
    }
    cpa_commit();
}

__global__ __launch_bounds__(256) void flash_mma()
{
    extern __shared__ char sm[];
    uint32_t smb = s2u(sm);
    float* redm = (float*)(sm + FREDM);
    float* reds = (float*)(sm + FREDS);

    const int t = threadIdx.x, wid = t >> 5, lane = t & 31;
    const int g = lane >> 2, tg = lane & 3;
    const int mt = wid & 3, nh = wid >> 2;
    const int b = blockIdx.z, h = blockIdx.y, q0 = blockIdx.x * 64;

    const size_t hb = ((size_t)(b * NUM_HEADS + h)) * S_LEN * HEAD_DIM;
    const size_t qoff = hb + (size_t)q0 * HEAD_DIM;

    // load Q hi/lo
#pragma unroll
    for (int i = 0; i < 2; i++) {
        int idx = t + 256 * i;
        int row = idx >> 3, cc = idx & 7;
        cpa16(smb + FQHI + SWF(row, cc), g_Qhi + qoff + row * HEAD_DIM + cc * 8);
        cpa16(smb + FQLO + SWF(row, cc), g_Qlo + qoff + row * HEAD_DIM + cc * 8);
    }
    cpa_commit();
    f_load_kv(0, 0, smb, t, hb);
    f_load_kv(1, 1, smb, t, hb);

    const int r0 = mt * 16 + g, r1 = r0 + 8;
    float mp0 = -1e30f, mp1 = -1e30f, l0 = 0.f, l1 = 0.f;
    float o[4][4];
#pragma unroll
    for (int nt = 0; nt < 4; nt++)
#pragma unroll
        for (int k = 0; k < 4; k++) o[nt][k] = 0.f;

    for (int it = 0; it < 32; it++) {
        if (it < 31) cpa_wait<1>(); else cpa_wait<0>();
        __syncthreads();
        uint32_t kb = smb + FKV + (it & 1) * FKV_STAGE;

        // ---- S = Q K^T (3 split terms) ----
        float s4[4][4];
#pragma unroll
        for (int nt = 0; nt < 4; nt++)
#pragma unroll
            for (int k = 0; k < 4; k++) s4[nt][k] = 0.f;

#pragma unroll
        for (int term = 0; term < 3; term++) {
            uint32_t qb = (term == 2) ? smb + FQLO : smb + FQHI;
            uint32_t kk = (term == 1) ? kb + 8192 : kb;
#pragma unroll
            for (int k16 = 0; k16 < 4; k16++) {
                int cc = k16 * 2;
                uint32_t af[4];
                {
                    int row = mt * 16 + (lane & 15);
                    int ch = cc + (lane >> 4);
                    ldsm4(af, qb + SWF(row, ch));
                }
                uint32_t bf[4][2];
#pragma unroll
                for (int bt = 0; bt < 2; bt++) {
                    int row = nh * 32 + bt * 16 + ((lane >> 4) << 3) + (lane & 7);
                    int ch = cc + ((lane >> 3) & 1);
                    uint32_t r4[4];
                    ldsm4(r4, kk + SWF(row, ch));
                    bf[2 * bt][0] = r4[0]; bf[2 * bt][1] = r4[1];
                    bf[2 * bt + 1][0] = r4[2]; bf[2 * bt + 1][1] = r4[3];
                }
#pragma unroll
                for (int nt = 0; nt < 4; nt++)
                    mma16816(s4[nt], af, bf[nt]);
            }
        }

        // ---- online softmax ----
        float mx0 = -1e30f, mx1 = -1e30f;
#pragma unroll
        for (int nt = 0; nt < 4; nt++) {
            mx0 = fmaxf(mx0, fmaxf(s4[nt][0], s4[nt][1]));
            mx1 = fmaxf(mx1, fmaxf(s4[nt][2], s4[nt][3]));
        }
        mx0 = fmaxf(mx0, __shfl_xor_sync(0xffffffffu, mx0, 1));
        mx0 = fmaxf(mx0, __shfl_xor_sync(0xffffffffu, mx0, 2));
        mx1 = fmaxf(mx1, __shfl_xor_sync(0xffffffffu, mx1, 1));
        mx1 = fmaxf(mx1, __shfl_xor_sync(0xffffffffu, mx1, 2));
        if (tg == 0) { redm[nh * 64 + r0] = mx0; redm[nh * 64 + r1] = mx1; }
        __syncthreads();
        float Mn0 = fmaxf(fmaxf(redm[r0], redm[64 + r0]), mp0);
        float Mn1 = fmaxf(fmaxf(redm[r1], redm[64 + r1]), mp1);
        float corr0 = fexp(mp0 - Mn0);
        float corr1 = fexp(mp1 - Mn1);

        float ls0 = 0.f, ls1 = 0.f;
#pragma unroll
        for (int nt = 0; nt < 4; nt++) {
            s4[nt][0] = fexp(s4[nt][0] - Mn0);
            s4[nt][1] = fexp(s4[nt][1] - Mn0);
            s4[nt][2] = fexp(s4[nt][2] - Mn1);
            s4[nt][3] = fexp(s4[nt][3] - Mn1);
            ls0 += s4[nt][0] + s4[nt][1];
            ls1 += s4[nt][2] + s4[nt][3];
        }
        ls0 += __shfl_xor_sync(0xffffffffu, ls0, 1);
        ls0 += __shfl_xor_sync(0xffffffffu, ls0, 2);
        ls1 += __shfl_xor_sync(0xffffffffu, ls1, 1);
        ls1 += __shfl_xor_sync(0xffffffffu, ls1, 2);
        if (tg == 0) { reds[nh * 64 + r0] = ls0; reds[nh * 64 + r1] = ls1; }

        // write P hi/lo into smem for the PV mma
#pragma unroll
        for (int nt = 0; nt < 4; nt++) {
            int cch = nh * 4 + nt;
            uint32_t a0 = smb + FPHI + SWF(r0, cch) + tg * 4;
            uint32_t a1 = smb + FPHI + SWF(r1, cch) + tg * 4;
            uint32_t a2 = smb + FPLO + SWF(r0, cch) + tg * 4;
            uint32_t a3 = smb + FPLO + SWF(r1, cch) + tg * 4;
            __nv_bfloat16 h0 = __float2bfloat16(s4[nt][0]);
            __nv_bfloat16 h1 = __float2bfloat16(s4[nt][1]);
            __nv_bfloat16 h2 = __float2bfloat16(s4[nt][2]);
            __nv_bfloat16 h3 = __float2bfloat16(s4[nt][3]);
            __nv_bfloat162 P0; P0.x = h0; P0.y = h1;
            __nv_bfloat162 P1; P1.x = h2; P1.y = h3;
            *(__nv_bfloat162*)(sm + (a0 - smb)) = P0;
            *(__nv_bfloat162*)(sm + (a1 - smb)) = P1;
            __nv_bfloat162 L0, L1;
            L0.x = __float2bfloat16(s4[nt][0] - __bfloat162float(h0));
            L0.y = __float2bfloat16(s4[nt][1] - __bfloat162float(h1));
            L1.x = __float2bfloat16(s4[nt][2] - __bfloat162float(h2));
            L1.y = __float2bfloat16(s4[nt][3] - __bfloat162float(h3));
            *(__nv_bfloat162*)(sm + (a2 - smb)) = L0;
            *(__nv_bfloat162*)(sm + (a3 - smb)) = L1;
        }
        __syncthreads();

        float sum0 = reds[r0] + reds[64 + r0];
        float sum1 = reds[r1] + reds[64 + r1];
        l0 = l0 * corr0 + sum0; mp0 = Mn0;
        l1 = l1 * corr1 + sum1; mp1 = Mn1;
#pragma unroll
        for (int nt = 0; nt < 4; nt++) {
            o[nt][0] *= corr0; o[nt][1] *= corr0;
            o[nt][2] *= corr1; o[nt][3] *= corr1;
        }

        // ---- O += P V (3 split terms) ----
#pragma unroll
        for (int term = 0; term < 3; term++) {
            uint32_t pb = (term == 2) ? smb + FPLO : smb + FPHI;
            uint32_t vb = kb + ((term == 1) ? 24576 : 16384);
#pragma unroll
            for (int k16 = 0; k16 < 4; k16++) {
                uint32_t af[4];
                {
                    int row = mt * 16 + (lane & 15);
                    int ch = k16 * 2 + (lane >> 4);
                    ldsm4(af, pb + SWF(row, ch));
                }
                uint32_t bf[4][2];
#pragma unroll
                for (int bt = 0; bt < 2; bt++) {
                    int rowv = k16 * 16 + ((lane >> 3) & 1) * 8 + (lane & 7);
                    int dch = nh * 4 + bt * 2 + (lane >> 4);
                    uint32_t r4[4];
                    ldsm4t(r4, vb + SWF(rowv, dch));
                    bf[2 * bt][0] = r4[0]; bf[2 * bt][1] = r4[1];
                    bf[2 * bt + 1][0] = r4[2]; bf[2 * bt + 1][1] = r4[3];
                }
#pragma unroll
                for (int nt = 0; nt < 4; nt++)
                    mma16816(o[nt], af, bf[nt]);
            }
        }
        __syncthreads();
        if (it + 2 < 32) f_load_kv(it + 2, it & 1, smb, t, hb);
    }

    // epilogue -> g_AO hi/lo
    float inv0 = 1.0f / l0, inv1 = 1.0f / l1;
#pragma unroll
    for (int nt = 0; nt < 4; nt++) {
        int col = nh * 32 + nt * 8 + tg * 2;
        size_t o0 = ((size_t)(b * S_LEN + q0 + r0)) * D_MODEL + h * HEAD_DIM + col;
        size_t o1 = ((size_t)(b * S_LEN + q0 + r1)) * D_MODEL + h * HEAD_DIM + col;
        split_store(o[nt][0] * inv0, o[nt][1] * inv0, g_AOhi, g_AOlo, o0);
        split_store(o[nt][2] * inv1, o[nt][3] * inv1, g_AOhi, g_AOlo, o1);
    }
}

// ---------------------------------------------------------------------------
extern "C" void kernel_launch(void* const* d_in, const int* in_sizes, int n_in,
                              void* d_out, int out_size)
{
    const float* X    = (const float*)d_in[0];
    const float* Wqkv = (const float*)d_in[1];
    const float* bqkv = (const float*)d_in[2];
    const float* Wo   = (const float*)d_in[3];
    const float* bo   = (const float*)d_in[4];
    float* out = (float*)d_out;

    cudaFuncSetAttribute((const void*)gemm_mma,
                         cudaFuncAttributeMaxDynamicSharedMemorySize, GEMM_SMEM);
    cudaFuncSetAttribute((const void*)flash_mma,
                         cudaFuncAttributeMaxDynamicSharedMemorySize, FLASH_SMEM);

    __nv_bfloat16 *xhi, *xlo, *wqhi, *wqlo, *wohi, *wolo, *aohi, *aolo;
    cudaGetSymbolAddress((void**)&xhi,  g_Xhi);
    cudaGetSymbolAddress((void**)&xlo,  g_Xlo);
    cudaGetSymbolAddress((void**)&wqhi, g_Wqkvhi);
    cudaGetSymbolAddress((void**)&wqlo, g_Wqkvlo);
    cudaGetSymbolAddress((void**)&wohi, g_Wohi);
    cudaGetSymbolAddress((void**)&wolo, g_Wolo);
    cudaGetSymbolAddress((void**)&aohi, g_AOhi);
    cudaGetSymbolAddress((void**)&aolo, g_AOlo);

    split_kernel<<<(M_ROWS * D_MODEL / 4 + 255) / 256, 256>>>(
        X, xhi, xlo, M_ROWS * D_MODEL / 4);
    split_kernel<<<(3 * D_MODEL * D_MODEL / 4 + 255) / 256, 256>>>(
        Wqkv, wqhi, wqlo, 3 * D_MODEL * D_MODEL / 4);
    split_kernel<<<(D_MODEL * D_MODEL / 4 + 255) / 256, 256>>>(
        Wo, wohi, wolo, D_MODEL * D_MODEL / 4);

    gemm_mma<<<dim3(3 * D_MODEL / 128, M_ROWS / 128), 256, GEMM_SMEM>>>(
        xhi, xlo, wqhi, wqlo, bqkv, nullptr, 0);

    flash_mma<<<dim3(S_LEN / 64, NUM_HEADS, BATCH), 256, FLASH_SMEM>>>();

    gemm_mma<<<dim3(D_MODEL / 128, M_ROWS / 128), 256, GEMM_SMEM>>>(
        aohi, aolo, wohi, wolo, bo, out, 1);
}

// round 4
// speedup vs baseline: 2.6754x; 1.0552x over previous
#include <cuda_runtime.h>
#include <cuda_bf16.h>
#include <cstdint>
#include <cstddef>

#define D_MODEL 1024
#define NUM_HEADS 16
#define HEAD_DIM 64
#define S_LEN 2048
#define BATCH 2
#define M_ROWS (BATCH * S_LEN)      // 4096

// ---------------------------------------------------------------------------
// Scratch (static device globals)
// ---------------------------------------------------------------------------
__device__ __nv_bfloat16 g_Qhi[BATCH * NUM_HEADS * S_LEN * HEAD_DIM];
__device__ __nv_bfloat16 g_Qlo[BATCH * NUM_HEADS * S_LEN * HEAD_DIM];
__device__ __nv_bfloat16 g_Khi[BATCH * NUM_HEADS * S_LEN * HEAD_DIM];
__device__ __nv_bfloat16 g_Klo[BATCH * NUM_HEADS * S_LEN * HEAD_DIM];
__device__ __nv_bfloat16 g_Vhi[BATCH * NUM_HEADS * S_LEN * HEAD_DIM];
__device__ __nv_bfloat16 g_Vlo[BATCH * NUM_HEADS * S_LEN * HEAD_DIM];
__device__ __nv_bfloat16 g_Xhi[M_ROWS * D_MODEL];
__device__ __nv_bfloat16 g_Xlo[M_ROWS * D_MODEL];
__device__ __nv_bfloat16 g_Wqkvhi[3 * D_MODEL * D_MODEL];
__device__ __nv_bfloat16 g_Wqkvlo[3 * D_MODEL * D_MODEL];
__device__ __nv_bfloat16 g_Wohi[D_MODEL * D_MODEL];
__device__ __nv_bfloat16 g_Wolo[D_MODEL * D_MODEL];
__device__ __nv_bfloat16 g_AOhi[M_ROWS * D_MODEL];
__device__ __nv_bfloat16 g_AOlo[M_ROWS * D_MODEL];

// ---------------------------------------------------------------------------
// Helpers
// ---------------------------------------------------------------------------
__device__ __forceinline__ uint32_t s2u(const void* p) {
    uint32_t a;
    asm("{ .reg .u64 t; cvta.to.shared.u64 t, %1; cvt.u32.u64 %0, t; }"
        : "=r"(a) : "l"(p));
    return a;
}
__device__ __forceinline__ void cpa16(uint32_t dst, const void* src) {
    asm volatile("cp.async.cg.shared.global [%0], [%1], 16;\n"
                 :: "r"(dst), "l"(src));
}
__device__ __forceinline__ void cpa_commit() {
    asm volatile("cp.async.commit_group;\n" ::: "memory");
}
template <int N>
__device__ __forceinline__ void cpa_wait() {
    asm volatile("cp.async.wait_group %0;\n" :: "n"(N) : "memory");
}
__device__ __forceinline__ void ldsm4(uint32_t* r, uint32_t a) {
    asm volatile("ldmatrix.sync.aligned.m8n8.x4.shared.b16 {%0,%1,%2,%3}, [%4];"
                 : "=r"(r[0]), "=r"(r[1]), "=r"(r[2]), "=r"(r[3]) : "r"(a));
}
__device__ __forceinline__ void ldsm4t(uint32_t* r, uint32_t a) {
    asm volatile("ldmatrix.sync.aligned.m8n8.x4.trans.shared.b16 {%0,%1,%2,%3}, [%4];"
                 : "=r"(r[0]), "=r"(r[1]), "=r"(r[2]), "=r"(r[3]) : "r"(a));
}
__device__ __forceinline__ void mma16816(float* c, const uint32_t* a, const uint32_t* b) {
    asm volatile(
        "mma.sync.aligned.m16n8k16.row.col.f32.bf16.bf16.f32 "
        "{%0,%1,%2,%3}, {%4,%5,%6,%7}, {%8,%9}, {%0,%1,%2,%3};"
        : "+f"(c[0]), "+f"(c[1]), "+f"(c[2]), "+f"(c[3])
        : "r"(a[0]), "r"(a[1]), "r"(a[2]), "r"(a[3]), "r"(b[0]), "r"(b[1]));
}

// fast e^x on the FFMA pipe
__device__ __forceinline__ float fexp(float x) {
    x = fmaxf(x, -80.0f);
    float y = x * 1.4426950408889634f;
    float r = __fadd_rn(y, 12582912.0f);
    int   n = __float_as_int(r) - 0x4B400000;
    float f = y - __fsub_rn(r, 12582912.0f);
    float p = 1.5403e-4f;
    p = fmaf(p, f, 1.3333558e-3f);
    p = fmaf(p, f, 9.6181291e-3f);
    p = fmaf(p, f, 5.5504109e-2f);
    p = fmaf(p, f, 2.4022651e-1f);
    p = fmaf(p, f, 6.9314718e-1f);
    p = fmaf(p, f, 1.0f);
    return __int_as_float(__float_as_int(p) + (n << 23));
}

__device__ __forceinline__ void split_store(float v0, float v1,
                                            __nv_bfloat16* hi, __nv_bfloat16* lo,
                                            size_t off) {
    __nv_bfloat16 h0 = __float2bfloat16(v0), h1 = __float2bfloat16(v1);
    __nv_bfloat162 H; H.x = h0; H.y = h1;
    *reinterpret_cast<__nv_bfloat162*>(hi + off) = H;
    __nv_bfloat162 L;
    L.x = __float2bfloat16(v0 - __bfloat162float(h0));
    L.y = __float2bfloat16(v1 - __bfloat162float(h1));
    *reinterpret_cast<__nv_bfloat162*>(lo + off) = L;
}

#define SWA(row, ch) ((row) * 64 + ((((ch) ^ (((row) >> 1) & 3))) << 4))
#define SWF(row, ch) ((row) * 128 + ((((ch) ^ ((row) & 7))) << 4))

// ---------------------------------------------------------------------------
// Split fp32 -> bf16 hi + lo
// ---------------------------------------------------------------------------
__global__ __launch_bounds__(256) void split_kernel(
    const float* __restrict__ in, __nv_bfloat16* __restrict__ hi,
    __nv_bfloat16* __restrict__ lo, int n4)
{
    int i = blockIdx.x * blockDim.x + threadIdx.x;
    if (i >= n4) return;
    float4 v = ((const float4*)in)[i];
    split_store(v.x, v.y, hi, lo, (size_t)i * 4);
    split_store(v.z, v.w, hi, lo, (size_t)i * 4 + 2);
}

// ---------------------------------------------------------------------------
// mma.sync split-bf16 GEMM (unchanged from round 3)
// ---------------------------------------------------------------------------
#define G_STAGE 16384
#define GEMM_SMEM (4 * G_STAGE)

__device__ __forceinline__ void g_load_stage(
    int c, int s, uint32_t smb, int t, int m0, int n0,
    const __nv_bfloat16* Ahi, const __nv_bfloat16* Alo,
    const __nv_bfloat16* Bhi, const __nv_bfloat16* Blo)
{
    int ph = c >> 5;
    int kc = (c & 31) * 32;
    const __nv_bfloat16* Ag = (ph == 2) ? Alo : Ahi;
    const __nv_bfloat16* Bg = (ph == 1) ? Blo : Bhi;
    uint32_t sa = smb + s * G_STAGE;
    uint32_t sb = sa + 8192;
#pragma unroll
    for (int i = 0; i < 2; i++) {
        int idx = t + 256 * i;
        int row = idx >> 2, cc = idx & 3;
        cpa16(sa + SWA(row, cc), Ag + (size_t)(m0 + row) * D_MODEL + kc + cc * 8);
    }
#pragma unroll
    for (int i = 0; i < 2; i++) {
        int idx = t + 256 * i;
        int row = idx >> 2, cc = idx & 3;
        cpa16(sb + SWA(row, cc), Bg + (size_t)(n0 + row) * D_MODEL + kc + cc * 8);
    }
    cpa_commit();
}

__global__ __launch_bounds__(256) void gemm_mma(
    const __nv_bfloat16* __restrict__ Ahi, const __nv_bfloat16* __restrict__ Alo,
    const __nv_bfloat16* __restrict__ Bhi, const __nv_bfloat16* __restrict__ Blo,
    const float* __restrict__ bias, float* __restrict__ Cout, int mode)
{
    extern __shared__ char sm[];
    uint32_t smb = s2u(sm);
    const int t = threadIdx.x, wid = t >> 5, lane = t & 31;
    const int g = lane >> 2, tg = lane & 3;
    const int warp_m = wid & 1, warp_n = wid >> 1;
    const int m0 = blockIdx.y * 128, n0 = blockIdx.x * 128;

    float acc[4][4][4];
#pragma unroll
    for (int a = 0; a < 4; a++)
#pragma unroll
        for (int b = 0; b < 4; b++)
#pragma unroll
            for (int k = 0; k < 4; k++) acc[a][b][k] = 0.f;

    g_load_stage(0, 0, smb, t, m0, n0, Ahi, Alo, Bhi, Blo);
    g_load_stage(1, 1, smb, t, m0, n0, Ahi, Alo, Bhi, Blo);
    g_load_stage(2, 2, smb, t, m0, n0, Ahi, Alo, Bhi, Blo);

    for (int c = 0; c < 96; c++) {
        if (c < 94) cpa_wait<2>();
        else if (c == 94) cpa_wait<1>();
        else cpa_wait<0>();
        __syncthreads();
        if (c + 3 < 96)
            g_load_stage(c + 3, (c + 3) & 3, smb, t, m0, n0, Ahi, Alo, Bhi, Blo);

        uint32_t sa = smb + (c & 3) * G_STAGE;
        uint32_t sb = sa + 8192;
#pragma unroll
        for (int ks = 0; ks < 2; ks++) {
            int cc = ks * 2;
            uint32_t af[4][4];
#pragma unroll
            for (int mt = 0; mt < 4; mt++) {
                int row = warp_m * 64 + mt * 16 + (lane & 15);
                int ch = cc + (lane >> 4);
                ldsm4(af[mt], sa + SWA(row, ch));
            }
            uint32_t bf[4][2];
#pragma unroll
            for (int bt = 0; bt < 2; bt++) {
                int row = warp_n * 32 + bt * 16 + ((lane >> 4) << 3) + (lane & 7);
                int ch = cc + ((lane >> 3) & 1);
                uint32_t r4[4];
                ldsm4(r4, sb + SWA(row, ch));
                bf[2 * bt][0] = r4[0]; bf[2 * bt][1] = r4[1];
                bf[2 * bt + 1][0] = r4[2]; bf[2 * bt + 1][1] = r4[3];
            }
#pragma unroll
            for (int mt = 0; mt < 4; mt++)
#pragma unroll
                for (int nt = 0; nt < 4; nt++)
                    mma16816(acc[mt][nt], af[mt], bf[nt]);
        }
    }

#pragma unroll
    for (int mt = 0; mt < 4; mt++) {
#pragma unroll
        for (int nt = 0; nt < 4; nt++) {
            int n = n0 + warp_n * 32 + nt * 8 + tg * 2;
            float b0 = bias[n], b1 = bias[n + 1];
            int mrow = m0 + warp_m * 64 + mt * 16 + g;
            if (mode == 1) {
#pragma unroll
                for (int hh = 0; hh < 2; hh++) {
                    int m = mrow + hh * 8;
                    float2 v;
                    v.x = acc[mt][nt][hh * 2] + b0;
                    v.y = acc[mt][nt][hh * 2 + 1] + b1;
                    *(float2*)(Cout + (size_t)m * D_MODEL + n) = v;
                }
            } else {
                int h = n / 192;
                int r = n - h * 192;
                __nv_bfloat16 *dhi, *dlo; int d; float sc = 1.f;
                if (r < 64)       { dhi = g_Qhi; dlo = g_Qlo; d = r; sc = 0.125f; }
                else if (r < 128) { dhi = g_Khi; dlo = g_Klo; d = r - 64; }
                else              { dhi = g_Vhi; dlo = g_Vlo; d = r - 128; }
#pragma unroll
                for (int hh = 0; hh < 2; hh++) {
                    int m = mrow + hh * 8;
                    int bb = m >> 11, s = m & 2047;
                    size_t off = (((size_t)(bb * NUM_HEADS + h)) * S_LEN + s) * HEAD_DIM + d;
                    float v0 = (acc[mt][nt][hh * 2] + b0) * sc;
                    float v1 = (acc[mt][nt][hh * 2 + 1] + b1) * sc;
                    split_store(v0, v1, dhi, dlo, off);
                }
            }
        }
    }
}

// ---------------------------------------------------------------------------
// Flash attention v2: 128 q rows/CTA, 8 warps, each warp owns 16 rows x all
// 64 kv cols. P stays in registers (C-frag == A-frag layout). No cross-warp
// reductions, no P smem.
// ---------------------------------------------------------------------------
#define FQHI 0
#define FQLO 16384
#define FKV  32768           // stage: KHI +0, KLO +8192, VHI +16384, VLO +24576
#define FKV_STAGE 32768
#define FLASH_SMEM (FKV + 2 * FKV_STAGE)   // 98304

__device__ __forceinline__ void f_load_kv(int it, int s, uint32_t smb, int t,
                                          size_t hb)
{
    size_t base = hb + (size_t)it * 64 * HEAD_DIM;
    uint32_t sb = smb + FKV + s * FKV_STAGE;
    const __nv_bfloat16* srcs[4] = {g_Khi, g_Klo, g_Vhi, g_Vlo};
#pragma unroll
    for (int a = 0; a < 4; a++) {
#pragma unroll
        for (int i = 0; i < 2; i++) {
            int idx = t + 256 * i;
            int row = idx >> 3, cc = idx & 7;
            cpa16(sb + a * 8192 + SWF(row, cc), srcs[a] + base + row * HEAD_DIM + cc * 8);
        }
    }
    cpa_commit();
}

__global__ __launch_bounds__(256) void flash_mma()
{
    extern __shared__ char sm[];
    uint32_t smb = s2u(sm);

    const int t = threadIdx.x, wid = t >> 5, lane = t & 31;
    const int g = lane >> 2, tg = lane & 3;
    const int b = blockIdx.z, h = blockIdx.y, q0 = blockIdx.x * 128;

    const size_t hb = ((size_t)(b * NUM_HEADS + h)) * S_LEN * HEAD_DIM;
    const size_t qoff = hb + (size_t)q0 * HEAD_DIM;

    // load Q hi/lo (128 rows)
#pragma unroll
    for (int i = 0; i < 4; i++) {
        int idx = t + 256 * i;
        int row = idx >> 3, cc = idx & 7;
        cpa16(smb + FQHI + SWF(row, cc), g_Qhi + qoff + row * HEAD_DIM + cc * 8);
        cpa16(smb + FQLO + SWF(row, cc), g_Qlo + qoff + row * HEAD_DIM + cc * 8);
    }
    cpa_commit();
    f_load_kv(0, 0, smb, t, hb);
    f_load_kv(1, 1, smb, t, hb);

    // Q fragments into registers (warp-owned 16 rows)
    cpa_wait<2>();
    __syncthreads();
    uint32_t qhi[4][4], qlo[4][4];
#pragma unroll
    for (int k16 = 0; k16 < 4; k16++) {
        int row = wid * 16 + (lane & 15);
        int ch = 2 * k16 + (lane >> 4);
        ldsm4(qhi[k16], smb + FQHI + SWF(row, ch));
        ldsm4(qlo[k16], smb + FQLO + SWF(row, ch));
    }

    float mp0 = -1e30f, mp1 = -1e30f, l0 = 0.f, l1 = 0.f;
    float o[8][4];
#pragma unroll
    for (int nt = 0; nt < 8; nt++)
#pragma unroll
        for (int k = 0; k < 4; k++) o[nt][k] = 0.f;

    for (int it = 0; it < S_LEN / 64; it++) {
        if (it < S_LEN / 64 - 1) cpa_wait<1>(); else cpa_wait<0>();
        __syncthreads();
        uint32_t kb = smb + FKV + (it & 1) * FKV_STAGE;

        // ---- S = Q K^T (Qhi*Khi + Qlo*Khi + Qhi*Klo) ----
        float s4[8][4];
#pragma unroll
        for (int nt = 0; nt < 8; nt++)
#pragma unroll
            for (int k = 0; k < 4; k++) s4[nt][k] = 0.f;

#pragma unroll
        for (int k16 = 0; k16 < 4; k16++) {
            int cc = 2 * k16;
#pragma unroll
            for (int bt = 0; bt < 4; bt++) {
                int row = bt * 16 + ((lane >> 4) << 3) + (lane & 7);
                int chsel = cc + ((lane >> 3) & 1);
                uint32_t rh[4], rl[4];
                ldsm4(rh, kb + SWF(row, chsel));          // Khi
                ldsm4(rl, kb + 8192 + SWF(row, chsel));   // Klo
                mma16816(s4[2 * bt],     qhi[k16], rh);
                mma16816(s4[2 * bt + 1], qhi[k16], rh + 2);
                mma16816(s4[2 * bt],     qlo[k16], rh);
                mma16816(s4[2 * bt + 1], qlo[k16], rh + 2);
                mma16816(s4[2 * bt],     qhi[k16], rl);
                mma16816(s4[2 * bt + 1], qhi[k16], rl + 2);
            }
        }

        // ---- online softmax (within 4-lane group) ----
        float mx0 = -1e30f, mx1 = -1e30f;
#pragma unroll
        for (int nt = 0; nt < 8; nt++) {
            mx0 = fmaxf(mx0, fmaxf(s4[nt][0], s4[nt][1]));
            mx1 = fmaxf(mx1, fmaxf(s4[nt][2], s4[nt][3]));
        }
        mx0 = fmaxf(mx0, __shfl_xor_sync(0xffffffffu, mx0, 1));
        mx0 = fmaxf(mx0, __shfl_xor_sync(0xffffffffu, mx0, 2));
        mx1 = fmaxf(mx1, __shfl_xor_sync(0xffffffffu, mx1, 1));
        mx1 = fmaxf(mx1, __shfl_xor_sync(0xffffffffu, mx1, 2));
        float Mn0 = fmaxf(mp0, mx0), Mn1 = fmaxf(mp1, mx1);
        float corr0 = fexp(mp0 - Mn0), corr1 = fexp(mp1 - Mn1);
        mp0 = Mn0; mp1 = Mn1;

        float ls0 = 0.f, ls1 = 0.f;
#pragma unroll
        for (int nt = 0; nt < 8; nt++) {
            s4[nt][0] = fexp(s4[nt][0] - Mn0);
            s4[nt][1] = fexp(s4[nt][1] - Mn0);
            s4[nt][2] = fexp(s4[nt][2] - Mn1);
            s4[nt][3] = fexp(s4[nt][3] - Mn1);
            ls0 += s4[nt][0] + s4[nt][1];
            ls1 += s4[nt][2] + s4[nt][3];
        }
        ls0 += __shfl_xor_sync(0xffffffffu, ls0, 1);
        ls0 += __shfl_xor_sync(0xffffffffu, ls0, 2);
        ls1 += __shfl_xor_sync(0xffffffffu, ls1, 1);
        ls1 += __shfl_xor_sync(0xffffffffu, ls1, 2);
        l0 = l0 * corr0 + ls0;
        l1 = l1 * corr1 + ls1;

#pragma unroll
        for (int nt = 0; nt < 8; nt++) {
            o[nt][0] *= corr0; o[nt][1] *= corr0;
            o[nt][2] *= corr1; o[nt][3] *= corr1;
        }

        // pack P hi (C-frag layout == A-frag layout)
        uint32_t phi[8][2];
        float pr[8][4];
#pragma unroll
        for (int nt = 0; nt < 8; nt++) {
            __nv_bfloat162 h01 = __floats2bfloat162_rn(s4[nt][0], s4[nt][1]);
            __nv_bfloat162 h23 = __floats2bfloat162_rn(s4[nt][2], s4[nt][3]);
            phi[nt][0] = *(uint32_t*)&h01;
            phi[nt][1] = *(uint32_t*)&h23;
            pr[nt][0] = s4[nt][0] - __bfloat162float(h01.x);
            pr[nt][1] = s4[nt][1] - __bfloat162float(h01.y);
            pr[nt][2] = s4[nt][2] - __bfloat162float(h23.x);
            pr[nt][3] = s4[nt][3] - __bfloat162float(h23.y);
        }

        // ---- O += P V (Phi*Vhi + Plo*Vhi + Phi*Vlo) ----
        uint32_t vh = kb + 16384, vl = kb + 24576;
#pragma unroll
        for (int k16 = 0; k16 < 4; k16++) {
            uint32_t ahi[4] = {phi[2 * k16][0], phi[2 * k16][1],
                               phi[2 * k16 + 1][0], phi[2 * k16 + 1][1]};
            uint32_t alo[4];
            {
                __nv_bfloat162 l01 = __floats2bfloat162_rn(pr[2 * k16][0], pr[2 * k16][1]);
                __nv_bfloat162 l23 = __floats2bfloat162_rn(pr[2 * k16][2], pr[2 * k16][3]);
                __nv_bfloat162 m01 = __floats2bfloat162_rn(pr[2 * k16 + 1][0], pr[2 * k16 + 1][1]);
                __nv_bfloat162 m23 = __floats2bfloat162_rn(pr[2 * k16 + 1][2], pr[2 * k16 + 1][3]);
                alo[0] = *(uint32_t*)&l01; alo[1] = *(uint32_t*)&l23;
                alo[2] = *(uint32_t*)&m01; alo[3] = *(uint32_t*)&m23;
            }
#pragma unroll
            for (int bt = 0; bt < 4; bt++) {
                int rowv = k16 * 16 + ((lane >> 3) & 1) * 8 + (lane & 7);
                int dch = bt * 2 + (lane >> 4);
                uint32_t rv[4], rw[4];
                ldsm4t(rv, vh + SWF(rowv, dch));    // Vhi
                ldsm4t(rw, vl + SWF(rowv, dch));    // Vlo
                mma16816(o[2 * bt],     ahi, rv);
                mma16816(o[2 * bt + 1], ahi, rv + 2);
                mma16816(o[2 * bt],     alo, rv);
                mma16816(o[2 * bt + 1], alo, rv + 2);
                mma16816(o[2 * bt],     ahi, rw);
                mma16816(o[2 * bt + 1], ahi, rw + 2);
            }
        }
        __syncthreads();
        if (it + 2 < S_LEN / 64) f_load_kv(it + 2, it & 1, smb, t, hb);
    }

    // epilogue -> g_AO hi/lo
    float inv0 = 1.0f / l0, inv1 = 1.0f / l1;
    int r0 = q0 + wid * 16 + g;
#pragma unroll
    for (int nt = 0; nt < 8; nt++) {
        int col = h * HEAD_DIM + nt * 8 + tg * 2;
        size_t o0 = ((size_t)(b * S_LEN + r0)) * D_MODEL + col;
        size_t o1 = ((size_t)(b * S_LEN + r0 + 8)) * D_MODEL + col;
        split_store(o[nt][0] * inv0, o[nt][1] * inv0, g_AOhi, g_AOlo, o0);
        split_store(o[nt][2] * inv1, o[nt][3] * inv1, g_AOhi, g_AOlo, o1);
    }
}

// ---------------------------------------------------------------------------
extern "C" void kernel_launch(void* const* d_in, const int* in_sizes, int n_in,
                              void* d_out, int out_size)
{
    const float* X    = (const float*)d_in[0];
    const float* Wqkv = (const float*)d_in[1];
    const float* bqkv = (const float*)d_in[2];
    const float* Wo   = (const float*)d_in[3];
    const float* bo   = (const float*)d_in[4];
    float* out = (float*)d_out;

    cudaFuncSetAttribute((const void*)gemm_mma,
                         cudaFuncAttributeMaxDynamicSharedMemorySize, GEMM_SMEM);
    cudaFuncSetAttribute((const void*)flash_mma,
                         cudaFuncAttributeMaxDynamicSharedMemorySize, FLASH_SMEM);

    __nv_bfloat16 *xhi, *xlo, *wqhi, *wqlo, *wohi, *wolo, *aohi, *aolo;
    cudaGetSymbolAddress((void**)&xhi,  g_Xhi);
    cudaGetSymbolAddress((void**)&xlo,  g_Xlo);
    cudaGetSymbolAddress((void**)&wqhi, g_Wqkvhi);
    cudaGetSymbolAddress((void**)&wqlo, g_Wqkvlo);
    cudaGetSymbolAddress((void**)&wohi, g_Wohi);
    cudaGetSymbolAddress((void**)&wolo, g_Wolo);
    cudaGetSymbolAddress((void**)&aohi, g_AOhi);
    cudaGetSymbolAddress((void**)&aolo, g_AOlo);

    split_kernel<<<(M_ROWS * D_MODEL / 4 + 255) / 256, 256>>>(
        X, xhi, xlo, M_ROWS * D_MODEL / 4);
    split_kernel<<<(3 * D_MODEL * D_MODEL / 4 + 255) / 256, 256>>>(
        Wqkv, wqhi, wqlo, 3 * D_MODEL * D_MODEL / 4);
    split_kernel<<<(D_MODEL * D_MODEL / 4 + 255) / 256, 256>>>(
        Wo, wohi, wolo, D_MODEL * D_MODEL / 4);

    gemm_mma<<<dim3(3 * D_MODEL / 128, M_ROWS / 128), 256, GEMM_SMEM>>>(
        xhi, xlo, wqhi, wqlo, bqkv, nullptr, 0);

    flash_mma<<<dim3(S_LEN / 128, NUM_HEADS, BATCH), 256, FLASH_SMEM>>>();

    gemm_mma<<<dim3(D_MODEL / 128, M_ROWS / 128), 256, GEMM_SMEM>>>(
        aohi, aolo, wohi, wolo, bo, out, 1);
}

// round 5
// speedup vs baseline: 2.7370x; 1.0230x over previous
#include <cuda_runtime.h>
#include <cuda_bf16.h>
#include <cstdint>
#include <cstddef>

#define D_MODEL 1024
#define NUM_HEADS 16
#define HEAD_DIM 64
#define S_LEN 2048
#define BATCH 2
#define M_ROWS (BATCH * S_LEN)      // 4096

// ---------------------------------------------------------------------------
// Scratch
// ---------------------------------------------------------------------------
__device__ __nv_bfloat16 g_Qhi[BATCH * NUM_HEADS * S_LEN * HEAD_DIM];
__device__ __nv_bfloat16 g_Qlo[BATCH * NUM_HEADS * S_LEN * HEAD_DIM];
__device__ __nv_bfloat16 g_Khi[BATCH * NUM_HEADS * S_LEN * HEAD_DIM];
__device__ __nv_bfloat16 g_Klo[BATCH * NUM_HEADS * S_LEN * HEAD_DIM];
__device__ __nv_bfloat16 g_Vhi[BATCH * NUM_HEADS * S_LEN * HEAD_DIM];
__device__ __nv_bfloat16 g_Vlo[BATCH * NUM_HEADS * S_LEN * HEAD_DIM];
__device__ __nv_bfloat16 g_Xhi[M_ROWS * D_MODEL];
__device__ __nv_bfloat16 g_Xlo[M_ROWS * D_MODEL];
__device__ __nv_bfloat16 g_Wqkvhi[3 * D_MODEL * D_MODEL];
__device__ __nv_bfloat16 g_Wqkvlo[3 * D_MODEL * D_MODEL];
__device__ __nv_bfloat16 g_Wohi[D_MODEL * D_MODEL];
__device__ __nv_bfloat16 g_Wolo[D_MODEL * D_MODEL];
__device__ __nv_bfloat16 g_AOhi[M_ROWS * D_MODEL];
__device__ __nv_bfloat16 g_AOlo[M_ROWS * D_MODEL];

// ---------------------------------------------------------------------------
// Helpers
// ---------------------------------------------------------------------------
__device__ __forceinline__ uint32_t s2u(const void* p) {
    uint32_t a;
    asm("{ .reg .u64 t; cvta.to.shared.u64 t, %1; cvt.u32.u64 %0, t; }"
        : "=r"(a) : "l"(p));
    return a;
}
__device__ __forceinline__ void cpa16(uint32_t dst, const void* src) {
    asm volatile("cp.async.cg.shared.global [%0], [%1], 16;\n"
                 :: "r"(dst), "l"(src));
}
__device__ __forceinline__ void cpa_commit() {
    asm volatile("cp.async.commit_group;\n" ::: "memory");
}
template <int N>
__device__ __forceinline__ void cpa_wait() {
    asm volatile("cp.async.wait_group %0;\n" :: "n"(N) : "memory");
}
__device__ __forceinline__ void ldsm4(uint32_t* r, uint32_t a) {
    asm volatile("ldmatrix.sync.aligned.m8n8.x4.shared.b16 {%0,%1,%2,%3}, [%4];"
                 : "=r"(r[0]), "=r"(r[1]), "=r"(r[2]), "=r"(r[3]) : "r"(a));
}
__device__ __forceinline__ void ldsm4t(uint32_t* r, uint32_t a) {
    asm volatile("ldmatrix.sync.aligned.m8n8.x4.trans.shared.b16 {%0,%1,%2,%3}, [%4];"
                 : "=r"(r[0]), "=r"(r[1]), "=r"(r[2]), "=r"(r[3]) : "r"(a));
}
__device__ __forceinline__ void mma16816(float* c, const uint32_t* a, const uint32_t* b) {
    asm volatile(
        "mma.sync.aligned.m16n8k16.row.col.f32.bf16.bf16.f32 "
        "{%0,%1,%2,%3}, {%4,%5,%6,%7}, {%8,%9}, {%0,%1,%2,%3};"
        : "+f"(c[0]), "+f"(c[1]), "+f"(c[2]), "+f"(c[3])
        : "r"(a[0]), "r"(a[1]), "r"(a[2]), "r"(a[3]), "r"(b[0]), "r"(b[1]));
}

// fast e^x on the FFMA pipe
__device__ __forceinline__ float fexp(float x) {
    x = fmaxf(x, -80.0f);
    float y = x * 1.4426950408889634f;
    float r = __fadd_rn(y, 12582912.0f);
    int   n = __float_as_int(r) - 0x4B400000;
    float f = y - __fsub_rn(r, 12582912.0f);
    float p = 1.5403e-4f;
    p = fmaf(p, f, 1.3333558e-3f);
    p = fmaf(p, f, 9.6181291e-3f);
    p = fmaf(p, f, 5.5504109e-2f);
    p = fmaf(p, f, 2.4022651e-1f);
    p = fmaf(p, f, 6.9314718e-1f);
    p = fmaf(p, f, 1.0f);
    return __int_as_float(__float_as_int(p) + (n << 23));
}

__device__ __forceinline__ void split_store(float v0, float v1,
                                            __nv_bfloat16* hi, __nv_bfloat16* lo,
                                            size_t off) {
    __nv_bfloat16 h0 = __float2bfloat16(v0), h1 = __float2bfloat16(v1);
    __nv_bfloat162 H; H.x = h0; H.y = h1;
    *reinterpret_cast<__nv_bfloat162*>(hi + off) = H;
    __nv_bfloat162 L;
    L.x = __float2bfloat16(v0 - __bfloat162float(h0));
    L.y = __float2bfloat16(v1 - __bfloat162float(h1));
    *reinterpret_cast<__nv_bfloat162*>(lo + off) = L;
}

#define SWF(row, ch) ((row) * 128 + ((((ch) ^ ((row) & 7))) << 4))

// ---------------------------------------------------------------------------
// Split fp32 -> bf16 hi + lo
// ---------------------------------------------------------------------------
__global__ __launch_bounds__(256) void split_kernel(
    const float* __restrict__ in, __nv_bfloat16* __restrict__ hi,
    __nv_bfloat16* __restrict__ lo, int n4)
{
    int i = blockIdx.x * blockDim.x + threadIdx.x;
    if (i >= n4) return;
    float4 v = ((const float4*)in)[i];
    split_store(v.x, v.y, hi, lo, (size_t)i * 4);
    split_store(v.z, v.w, hi, lo, (size_t)i * 4 + 2);
}

// ---------------------------------------------------------------------------
// mma.sync split-bf16 GEMM: BK=64 per stage, 3 stages, prefetch at chunk end.
// ---------------------------------------------------------------------------
#define G_STAGE 32768
#define GEMM_SMEM (3 * G_STAGE)     // 98304

__device__ __forceinline__ void g_load_stage(
    int c, int s, uint32_t smb, int t, int m0, int n0,
    const __nv_bfloat16* Ahi, const __nv_bfloat16* Alo,
    const __nv_bfloat16* Bhi, const __nv_bfloat16* Blo)
{
    int ph = c >> 4;
    int kc = (c & 15) * 64;
    const __nv_bfloat16* Ag = (ph == 2) ? Alo : Ahi;
    const __nv_bfloat16* Bg = (ph == 1) ? Blo : Bhi;
    uint32_t sa = smb + s * G_STAGE;
    uint32_t sb = sa + 16384;
#pragma unroll
    for (int i = 0; i < 4; i++) {
        int idx = t + 256 * i;
        int row = idx >> 3, cc = idx & 7;
        cpa16(sa + SWF(row, cc), Ag + (size_t)(m0 + row) * D_MODEL + kc + cc * 8);
    }
#pragma unroll
    for (int i = 0; i < 4; i++) {
        int idx = t + 256 * i;
        int row = idx >> 3, cc = idx & 7;
        cpa16(sb + SWF(row, cc), Bg + (size_t)(n0 + row) * D_MODEL + kc + cc * 8);
    }
    cpa_commit();
}

__global__ __launch_bounds__(256, 2) void gemm_mma(
    const __nv_bfloat16* __restrict__ Ahi, const __nv_bfloat16* __restrict__ Alo,
    const __nv_bfloat16* __restrict__ Bhi, const __nv_bfloat16* __restrict__ Blo,
    const float* __restrict__ bias, float* __restrict__ Cout, int mode)
{
    extern __shared__ char sm[];
    uint32_t smb = s2u(sm);
    const int t = threadIdx.x, wid = t >> 5, lane = t & 31;
    const int g = lane >> 2, tg = lane & 3;
    const int warp_m = wid & 1, warp_n = wid >> 1;
    const int m0 = blockIdx.y * 128, n0 = blockIdx.x * 128;

    float acc[4][4][4];
#pragma unroll
    for (int a = 0; a < 4; a++)
#pragma unroll
        for (int b = 0; b < 4; b++)
#pragma unroll
            for (int k = 0; k < 4; k++) acc[a][b][k] = 0.f;

    g_load_stage(0, 0, smb, t, m0, n0, Ahi, Alo, Bhi, Blo);
    g_load_stage(1, 1, smb, t, m0, n0, Ahi, Alo, Bhi, Blo);
    g_load_stage(2, 2, smb, t, m0, n0, Ahi, Alo, Bhi, Blo);

    int stage = 0;
    for (int c = 0; c < 48; c++) {
        if (c < 46) cpa_wait<2>();
        else if (c == 46) cpa_wait<1>();
        else cpa_wait<0>();
        __syncthreads();

        uint32_t sa = smb + stage * G_STAGE;
        uint32_t sb = sa + 16384;
#pragma unroll
        for (int ks = 0; ks < 4; ks++) {
            int cc = ks * 2;
            uint32_t af[4][4];
#pragma unroll
            for (int mt = 0; mt < 4; mt++) {
                int row = warp_m * 64 + mt * 16 + (lane & 15);
                int ch = cc + (lane >> 4);
                ldsm4(af[mt], sa + SWF(row, ch));
            }
            uint32_t bf[4][2];
#pragma unroll
            for (int bt = 0; bt < 2; bt++) {
                int row = warp_n * 32 + bt * 16 + ((lane >> 4) << 3) + (lane & 7);
                int ch = cc + ((lane >> 3) & 1);
                uint32_t r4[4];
                ldsm4(r4, sb + SWF(row, ch));
                bf[2 * bt][0] = r4[0]; bf[2 * bt][1] = r4[1];
                bf[2 * bt + 1][0] = r4[2]; bf[2 * bt + 1][1] = r4[3];
            }
#pragma unroll
            for (int mt = 0; mt < 4; mt++)
#pragma unroll
                for (int nt = 0; nt < 4; nt++)
                    mma16816(acc[mt][nt], af[mt], bf[nt]);
        }

        if (c + 3 < 48) {
            __syncthreads();   // all warps finished reading this slot
            g_load_stage(c + 3, stage, smb, t, m0, n0, Ahi, Alo, Bhi, Blo);
        }
        stage = (stage == 2) ? 0 : stage + 1;
    }

#pragma unroll
    for (int mt = 0; mt < 4; mt++) {
#pragma unroll
        for (int nt = 0; nt < 4; nt++) {
            int n = n0 + warp_n * 32 + nt * 8 + tg * 2;
            float b0 = bias[n], b1 = bias[n + 1];
            int mrow = m0 + warp_m * 64 + mt * 16 + g;
            if (mode == 1) {
#pragma unroll
                for (int hh = 0; hh < 2; hh++) {
                    int m = mrow + hh * 8;
                    float2 v;
                    v.x = acc[mt][nt][hh * 2] + b0;
                    v.y = acc[mt][nt][hh * 2 + 1] + b1;
                    *(float2*)(Cout + (size_t)m * D_MODEL + n) = v;
                }
            } else {
                int h = n / 192;
                int r = n - h * 192;
                __nv_bfloat16 *dhi, *dlo; int d; float sc = 1.f;
                if (r < 64)       { dhi = g_Qhi; dlo = g_Qlo; d = r; sc = 0.125f; }
                else if (r < 128) { dhi = g_Khi; dlo = g_Klo; d = r - 64; }
                else              { dhi = g_Vhi; dlo = g_Vlo; d = r - 128; }
#pragma unroll
                for (int hh = 0; hh < 2; hh++) {
                    int m = mrow + hh * 8;
                    int bb = m >> 11, s = m & 2047;
                    size_t off = (((size_t)(bb * NUM_HEADS + h)) * S_LEN + s) * HEAD_DIM + d;
                    float v0 = (acc[mt][nt][hh * 2] + b0) * sc;
                    float v1 = (acc[mt][nt][hh * 2 + 1] + b1) * sc;
                    split_store(v0, v1, dhi, dlo, off);
                }
            }
        }
    }
}

// ---------------------------------------------------------------------------
// Flash attention: 128 q rows/CTA, 8 warps, split K/V commit groups,
// K prefetch overlapped with softmax+PV, 2 CTAs/SM.
// ---------------------------------------------------------------------------
#define FQHI 0
#define FQLO 16384
#define FKV  32768
#define FKV_STAGE 32768
#define FLASH_SMEM (FKV + 2 * FKV_STAGE)   // 98304

__device__ __forceinline__ void f_load_k(int it, int s, uint32_t smb, int t,
                                         size_t hb)
{
    size_t base = hb + (size_t)it * 64 * HEAD_DIM;
    uint32_t sb = smb + FKV + s * FKV_STAGE;
#pragma unroll
    for (int i = 0; i < 2; i++) {
        int idx = t + 256 * i;
        int row = idx >> 3, cc = idx & 7;
        cpa16(sb + SWF(row, cc), g_Khi + base + row * HEAD_DIM + cc * 8);
        cpa16(sb + 8192 + SWF(row, cc), g_Klo + base + row * HEAD_DIM + cc * 8);
    }
    cpa_commit();
}
__device__ __forceinline__ void f_load_v(int it, int s, uint32_t smb, int t,
                                         size_t hb)
{
    size_t base = hb + (size_t)it * 64 * HEAD_DIM;
    uint32_t sb = smb + FKV + s * FKV_STAGE + 16384;
#pragma unroll
    for (int i = 0; i < 2; i++) {
        int idx = t + 256 * i;
        int row = idx >> 3, cc = idx & 7;
        cpa16(sb + SWF(row, cc), g_Vhi + base + row * HEAD_DIM + cc * 8);
        cpa16(sb + 8192 + SWF(row, cc), g_Vlo + base + row * HEAD_DIM + cc * 8);
    }
    cpa_commit();
}

__global__ __launch_bounds__(256, 2) void flash_mma()
{
    extern __shared__ char sm[];
    uint32_t smb = s2u(sm);

    const int t = threadIdx.x, wid = t >> 5, lane = t & 31;
    const int g = lane >> 2, tg = lane & 3;
    const int b = blockIdx.z, h = blockIdx.y, q0 = blockIdx.x * 128;

    const size_t hb = ((size_t)(b * NUM_HEADS + h)) * S_LEN * HEAD_DIM;
    const size_t qoff = hb + (size_t)q0 * HEAD_DIM;

#pragma unroll
    for (int i = 0; i < 4; i++) {
        int idx = t + 256 * i;
        int row = idx >> 3, cc = idx & 7;
        cpa16(smb + FQHI + SWF(row, cc), g_Qhi + qoff + row * HEAD_DIM + cc * 8);
        cpa16(smb + FQLO + SWF(row, cc), g_Qlo + qoff + row * HEAD_DIM + cc * 8);
    }
    cpa_commit();
    f_load_k(0, 0, smb, t, hb);
    f_load_v(0, 0, smb, t, hb);
    f_load_k(1, 1, smb, t, hb);
    f_load_v(1, 1, smb, t, hb);

    cpa_wait<4>();
    __syncthreads();
    uint32_t qhi[4][4];
#pragma unroll
    for (int k16 = 0; k16 < 4; k16++) {
        int row = wid * 16 + (lane & 15);
        int ch = 2 * k16 + (lane >> 4);
        ldsm4(qhi[k16], smb + FQHI + SWF(row, ch));
    }

    float mp0 = -1e30f, mp1 = -1e30f, l0 = 0.f, l1 = 0.f;
    float o[8][4];
#pragma unroll
    for (int nt = 0; nt < 8; nt++)
#pragma unroll
        for (int k = 0; k < 4; k++) o[nt][k] = 0.f;

    for (int it = 0; it < S_LEN / 64; it++) {
        if (it < S_LEN / 64 - 1) cpa_wait<2>(); else cpa_wait<0>();
        __syncthreads();
        uint32_t kb = smb + FKV + (it & 1) * FKV_STAGE;

        float s4[8][4];
#pragma unroll
        for (int nt = 0; nt < 8; nt++)
#pragma unroll
            for (int k = 0; k < 4; k++) s4[nt][k] = 0.f;

#pragma unroll
        for (int k16 = 0; k16 < 4; k16++) {
            int cc = 2 * k16;
            uint32_t ql[4];
            {
                int row = wid * 16 + (lane & 15);
                int ch = cc + (lane >> 4);
                ldsm4(ql, smb + FQLO + SWF(row, ch));
            }
#pragma unroll
            for (int bt = 0; bt < 4; bt++) {
                int row = bt * 16 + ((lane >> 4) << 3) + (lane & 7);
                int chsel = cc + ((lane >> 3) & 1);
                uint32_t rh[4], rl[4];
                ldsm4(rh, kb + SWF(row, chsel));
                ldsm4(rl, kb + 8192 + SWF(row, chsel));
                mma16816(s4[2 * bt],     qhi[k16], rh);
                mma16816(s4[2 * bt + 1], qhi[k16], rh + 2);
                mma16816(s4[2 * bt],     ql, rh);
                mma16816(s4[2 * bt + 1], ql, rh + 2);
                mma16816(s4[2 * bt],     qhi[k16], rl);
                mma16816(s4[2 * bt + 1], qhi[k16], rl + 2);
            }
        }
        __syncthreads();
        if (it + 2 < S_LEN / 64)
            f_load_k(it + 2, it & 1, smb, t, hb);

        float mx0 = -1e30f, mx1 = -1e30f;
#pragma unroll
        for (int nt = 0; nt < 8; nt++) {
            mx0 = fmaxf(mx0, fmaxf(s4[nt][0], s4[nt][1]));
            mx1 = fmaxf(mx1, fmaxf(s4[nt][2], s4[nt][3]));
        }
        mx0 = fmaxf(mx0, __shfl_xor_sync(0xffffffffu, mx0, 1));
        mx0 = fmaxf(mx0, __shfl_xor_sync(0xffffffffu, mx0, 2));
        mx1 = fmaxf(mx1, __shfl_xor_sync(0xffffffffu, mx1, 1));
        mx1 = fmaxf(mx1, __shfl_xor_sync(0xffffffffu, mx1, 2));
        float Mn0 = fmaxf(mp0, mx0), Mn1 = fmaxf(mp1, mx1);
        float corr0 = fexp(mp0 - Mn0), corr1 = fexp(mp1 - Mn1);
        mp0 = Mn0; mp1 = Mn1;

        float ls0 = 0.f, ls1 = 0.f;
#pragma unroll
        for (int nt = 0; nt < 8; nt++) {
            s4[nt][0] = fexp(s4[nt][0] - Mn0);
            s4[nt][1] = fexp(s4[nt][1] - Mn0);
            s4[nt][2] = fexp(s4[nt][2] - Mn1);
            s4[nt][3] = fexp(s4[nt][3] - Mn1);
            ls0 += s4[nt][0] + s4[nt][1];
            ls1 += s4[nt][2] + s4[nt][3];
        }
        ls0 += __shfl_xor_sync(0xffffffffu, ls0, 1);
        ls0 += __shfl_xor_sync(0xffffffffu, ls0, 2);
        ls1 += __shfl_xor_sync(0xffffffffu, ls1, 1);
        ls1 += __shfl_xor_sync(0xffffffffu, ls1, 2);
        l0 = l0 * corr0 + ls0;
        l1 = l1 * corr1 + ls1;

#pragma unroll
        for (int nt = 0; nt < 8; nt++) {
            o[nt][0] *= corr0; o[nt][1] *= corr0;
            o[nt][2] *= corr1; o[nt][3] *= corr1;
        }

        uint32_t vh = kb + 16384, vl = kb + 24576;
#pragma unroll
        for (int k16 = 0; k16 < 4; k16++) {
            const float* sA = s4[2 * k16];
            const float* sB = s4[2 * k16 + 1];
            uint32_t ahi[4], alo[4];
            {
                __nv_bfloat162 h01 = __floats2bfloat162_rn(sA[0], sA[1]);
                __nv_bfloat162 h23 = __floats2bfloat162_rn(sA[2], sA[3]);
                __nv_bfloat162 m01 = __floats2bfloat162_rn(sB[0], sB[1]);
                __nv_bfloat162 m23 = __floats2bfloat162_rn(sB[2], sB[3]);
                ahi[0] = *(uint32_t*)&h01; ahi[1] = *(uint32_t*)&h23;
                ahi[2] = *(uint32_t*)&m01; ahi[3] = *(uint32_t*)&m23;
                __nv_bfloat162 r01 = __floats2bfloat162_rn(
                    sA[0] - __bfloat162float(h01.x), sA[1] - __bfloat162float(h01.y));
                __nv_bfloat162 r23 = __floats2bfloat162_rn(
                    sA[2] - __bfloat162float(h23.x), sA[3] - __bfloat162float(h23.y));
                __nv_bfloat162 s01 = __floats2bfloat162_rn(
                    sB[0] - __bfloat162float(m01.x), sB[1] - __bfloat162float(m01.y));
                __nv_bfloat162 s23 = __floats2bfloat162_rn(
                    sB[2] - __bfloat162float(m23.x), sB[3] - __bfloat162float(m23.y));
                alo[0] = *(uint32_t*)&r01; alo[1] = *(uint32_t*)&r23;
                alo[2] = *(uint32_t*)&s01; alo[3] = *(uint32_t*)&s23;
            }
#pragma unroll
            for (int bt = 0; bt < 4; bt++) {
                int rowv = k16 * 16 + ((lane >> 3) & 1) * 8 + (lane & 7);
                int dch = bt * 2 + (lane >> 4);
                uint32_t rv[4], rw[4];
                ldsm4t(rv, vh + SWF(rowv, dch));
                ldsm4t(rw, vl + SWF(rowv, dch));
                mma16816(o[2 * bt],     ahi, rv);
                mma16816(o[2 * bt + 1], ahi, rv + 2);
                mma16816(o[2 * bt],     alo, rv);
                mma16816(o[2 * bt + 1], alo, rv + 2);
                mma16816(o[2 * bt],     ahi, rw);
                mma16816(o[2 * bt + 1], ahi, rw + 2);
            }
        }
        __syncthreads();
        if (it + 2 < S_LEN / 64)
            f_load_v(it + 2, it & 1, smb, t, hb);
    }

    float inv0 = 1.0f / l0, inv1 = 1.0f / l1;
    int r0 = q0 + wid * 16 + g;
#pragma unroll
    for (int nt = 0; nt < 8; nt++) {
        int col = h * HEAD_DIM + nt * 8 + tg * 2;
        size_t o0 = ((size_t)(b * S_LEN + r0)) * D_MODEL + col;
        size_t o1 = ((size_t)(b * S_LEN + r0 + 8)) * D_MODEL + col;
        split_store(o[nt][0] * inv0, o[nt][1] * inv0, g_AOhi, g_AOlo, o0);
        split_store(o[nt][2] * inv1, o[nt][3] * inv1, g_AOhi, g_AOlo, o1);
    }
}

// ---------------------------------------------------------------------------
extern "C" void kernel_launch(void* const* d_in, const int* in_sizes, int n_in,
                              void* d_out, int out_size)
{
    const float* X    = (const float*)d_in[0];
    const float* Wqkv = (const float*)d_in[1];
    const float* bqkv = (const float*)d_in[2];
    const float* Wo   = (const float*)d_in[3];
    const float* bo   = (const float*)d_in[4];
    float* out = (float*)d_out;

    cudaFuncSetAttribute((const void*)gemm_mma,
                         cudaFuncAttributeMaxDynamicSharedMemorySize, GEMM_SMEM);
    cudaFuncSetAttribute((const void*)flash_mma,
                         cudaFuncAttributeMaxDynamicSharedMemorySize, FLASH_SMEM);

    __nv_bfloat16 *xhi, *xlo, *wqhi, *wqlo, *wohi, *wolo, *aohi, *aolo;
    cudaGetSymbolAddress((void**)&xhi,  g_Xhi);
    cudaGetSymbolAddress((void**)&xlo,  g_Xlo);
    cudaGetSymbolAddress((void**)&wqhi, g_Wqkvhi);
    cudaGetSymbolAddress((void**)&wqlo, g_Wqkvlo);
    cudaGetSymbolAddress((void**)&wohi, g_Wohi);
    cudaGetSymbolAddress((void**)&wolo, g_Wolo);
    cudaGetSymbolAddress((void**)&aohi, g_AOhi);
    cudaGetSymbolAddress((void**)&aolo, g_AOlo);

    split_kernel<<<(M_ROWS * D_MODEL / 4 + 255) / 256, 256>>>(
        X, xhi, xlo, M_ROWS * D_MODEL / 4);
    split_kernel<<<(3 * D_MODEL * D_MODEL / 4 + 255) / 256, 256>>>(
        Wqkv, wqhi, wqlo, 3 * D_MODEL * D_MODEL / 4);
    split_kernel<<<(D_MODEL * D_MODEL / 4 + 255) / 256, 256>>>(
        Wo, wohi, wolo, D_MODEL * D_MODEL / 4);

    gemm_mma<<<dim3(3 * D_MODEL / 128, M_ROWS / 128), 256, GEMM_SMEM>>>(
        xhi, xlo, wqhi, wqlo, bqkv, nullptr, 0);

    flash_mma<<<dim3(S_LEN / 128, NUM_HEADS, BATCH), 256, FLASH_SMEM>>>();

    gemm_mma<<<dim3(D_MODEL / 128, M_ROWS / 128), 256, GEMM_SMEM>>>(
        aohi, aolo, wohi, wolo, bo, out, 1);
}